// round 15
// baseline (speedup 1.0000x reference)
#include <cuda_runtime.h>
#include <cuda_fp16.h>
#include <cstdint>

// Shapes (fixed by reference setup_inputs)
#define NROWS 16384
#define DDIM  512
#define DC    16
#define KCB   8192
#define LN_EPS 1e-5f

// ---------------- device scratch (no allocation allowed) --------------------
__device__ __half g_h1h[NROWS * DC], g_h2h[NROWS * DC];
__device__ __half g_c1h[KCB * DC],   g_c2h[KCB * DC];
__device__ float  g_hc2[KCB];        // 0.5 * sum c^2

// ---------------- helpers ---------------------------------------------------
__device__ __forceinline__ void split2(float v, __half& s1, __half& s2) {
    s1 = __float2half_rn(v);
    s2 = __float2half_rn(v - __half2float(s1));
}
__device__ __forceinline__ uint32_t pack_h2(__half lo, __half hi) {
    uint16_t a = __half_as_ushort(lo), b = __half_as_ushort(hi);
    return (uint32_t)a | ((uint32_t)b << 16);
}

__device__ __forceinline__ void mma_fp16(float& d0, float& d1, float& d2, float& d3,
                                         uint32_t a0, uint32_t a1, uint32_t a2, uint32_t a3,
                                         uint32_t b0, uint32_t b1) {
    asm volatile(
        "mma.sync.aligned.m16n8k16.row.col.f32.f16.f16.f32 "
        "{%0,%1,%2,%3}, {%4,%5,%6,%7}, {%8,%9}, {%0,%1,%2,%3};"
        : "+f"(d0), "+f"(d1), "+f"(d2), "+f"(d3)
        : "r"(a0), "r"(a1), "r"(a2), "r"(a3), "r"(b0), "r"(b1));
}

__device__ __forceinline__ void ldsm_x4(uint32_t& r0, uint32_t& r1,
                                        uint32_t& r2, uint32_t& r3, uint32_t saddr) {
    asm volatile("ldmatrix.sync.aligned.m8n8.x4.shared.b16 {%0,%1,%2,%3}, [%4];"
                 : "=r"(r0), "=r"(r1), "=r"(r2), "=r"(r3) : "r"(saddr));
}

// ---------------- kernel 0: codebook prep (fp16 split-2 + half-norms) -------
__global__ void __launch_bounds__(128) k_prep(const float* __restrict__ cb) {
    int k = blockIdx.x * blockDim.x + threadIdx.x;
    if (k >= KCB) return;
    const float4* c4 = (const float4*)(cb + (size_t)k * DC);
    float4 q0 = c4[0], q1 = c4[1], q2 = c4[2], q3 = c4[3];
    float cv[DC] = {q0.x, q0.y, q0.z, q0.w, q1.x, q1.y, q1.z, q1.w,
                    q2.x, q2.y, q2.z, q2.w, q3.x, q3.y, q3.z, q3.w};
    float c2 = 0.f;
#pragma unroll
    for (int j = 0; j < DC; j++) c2 = fmaf(cv[j], cv[j], c2);
    g_hc2[k] = 0.5f * c2;

    uint32_t p1[8], p2[8];
#pragma unroll
    for (int j = 0; j < 8; j++) {
        __half a1, a2, b1, b2;
        split2(cv[2 * j], a1, a2);
        split2(cv[2 * j + 1], b1, b2);
        p1[j] = pack_h2(a1, b1);
        p2[j] = pack_h2(a2, b2);
    }
    ((uint4*)&g_c1h[k * DC])[0] = *(uint4*)&p1[0];
    ((uint4*)&g_c1h[k * DC])[1] = *(uint4*)&p1[4];
    ((uint4*)&g_c2h[k * DC])[0] = *(uint4*)&p2[0];
    ((uint4*)&g_c2h[k * DC])[1] = *(uint4*)&p2[4];
}

// ---------------- kernel 1: projection + LayerNorm -> split2(-h) ------------
__global__ void __launch_bounds__(256) k_proj(
    const float* __restrict__ x, const float* __restrict__ W)
{
    const int warp = threadIdx.x >> 5;
    const int lane = threadIdx.x & 31;
    const int rowBase = (blockIdx.x * 8 + warp) * 4;

    float acc[4][DC];
#pragma unroll
    for (int r = 0; r < 4; r++)
#pragma unroll
        for (int j = 0; j < DC; j++) acc[r][j] = 0.f;

#pragma unroll 2
    for (int it = 0; it < DDIM / 32; it++) {
        const int d = it * 32 + lane;
        float wv[DC];
#pragma unroll
        for (int j = 0; j < DC; j++) wv[j] = W[j * DDIM + d];
#pragma unroll
        for (int r = 0; r < 4; r++) {
            float xv = x[(size_t)(rowBase + r) * DDIM + d];
#pragma unroll
            for (int j = 0; j < DC; j++)
                acc[r][j] = fmaf(xv, wv[j], acc[r][j]);
        }
    }

#pragma unroll
    for (int r = 0; r < 4; r++) {
        const int row = rowBase + r;
#pragma unroll
        for (int j = 0; j < DC; j++) {
#pragma unroll
            for (int ofs = 16; ofs > 0; ofs >>= 1)
                acc[r][j] += __shfl_xor_sync(0xFFFFFFFFu, acc[r][j], ofs);
        }

        float s = 0.f;
#pragma unroll
        for (int j = 0; j < DC; j++) s += acc[r][j];
        float mu = s * (1.0f / DC);
        float v = 0.f;
#pragma unroll
        for (int j = 0; j < DC; j++) { float d = acc[r][j] - mu; v = fmaf(d, d, v); }
        float denom = sqrtf(v * (1.0f / DC) + LN_EPS);

        if (lane < 8) {
            float e0 = (mu - acc[r][2 * lane]) / denom;
            float e1 = (mu - acc[r][2 * lane + 1]) / denom;
            __half a1, a2, b1, b2;
            split2(e0, a1, a2);
            split2(e1, b1, b2);
            ((uint32_t*)&g_h1h[row * DC])[lane] = pack_h2(a1, b1);
            ((uint32_t*)&g_h2h[row * DC])[lane] = pack_h2(a2, b2);
        }
    }
}

// ---------------- kernel 2: tensor-core distance + argmin (4 split-K groups) -
// 256 blocks x 512 threads (16 warps = 4 groups x 4 warps). Block owns 64 rows;
// group g scans chunks 4t+g of 64 codes; smem merge at the end.
#define CHUNK 64
#define NGRP  4
__global__ void __launch_bounds__(512) k_dist(float* __restrict__ out) {
    __shared__ __half smC[NGRP][2][2][CHUNK * DC];  // 32 KB
    __shared__ float  smH[NGRP][2][CHUNK];          // 2 KB
    __shared__ float  mv[NGRP][64];
    __shared__ int    mi[NGRP][64];

    const int tid    = threadIdx.x;
    const int warp   = tid >> 5;
    const int lane   = tid & 31;
    const int gid    = warp >> 2;        // 0..3 code-group
    const int w4     = warp & 3;         // row-quad
    const int tid128 = tid & 127;
    const int row0   = blockIdx.x * 64 + w4 * 16;
    const int r4     = lane >> 2;
    const int kp     = (lane & 3) * 2;

    // loop-invariant A fragments (layout validated R10-R14)
    uint32_t a1[4], a2[4];
    a1[0] = *(const uint32_t*)&g_h1h[(row0 + r4) * DC + kp];
    a1[1] = *(const uint32_t*)&g_h1h[(row0 + 8 + r4) * DC + kp];
    a1[2] = *(const uint32_t*)&g_h1h[(row0 + r4) * DC + kp + 8];
    a1[3] = *(const uint32_t*)&g_h1h[(row0 + 8 + r4) * DC + kp + 8];
    a2[0] = *(const uint32_t*)&g_h2h[(row0 + r4) * DC + kp];
    a2[1] = *(const uint32_t*)&g_h2h[(row0 + 8 + r4) * DC + kp];
    a2[2] = *(const uint32_t*)&g_h2h[(row0 + r4) * DC + kp + 8];
    a2[3] = *(const uint32_t*)&g_h2h[(row0 + 8 + r4) * DC + kp + 8];

    // stage one 64-code chunk: 128 uint4 per split, 1 per thread (128 thr/group)
    auto stage = [&](int ch, int buf) {
        ((uint4*)smC[gid][buf][0])[tid128] = ((const uint4*)g_c1h)[ch * 128 + tid128];
        ((uint4*)smC[gid][buf][1])[tid128] = ((const uint4*)g_c2h)[ch * 128 + tid128];
        if (tid128 < 16)
            ((uint4*)smH[gid][buf])[tid128] = ((const uint4*)(g_hc2 + ch * CHUNK))[tid128];
    };
    auto gbar = [&]() {
        asm volatile("bar.sync %0, 128;" :: "r"(gid + 1) : "memory");
    };

    const int coderow = (lane & 7) + ((lane & 16) >> 1);
    const int khalf   = (lane >> 3) & 1;
    const uint32_t lmoff = (uint32_t)(coderow * 32 + khalf * 16);

    float bv[8];
    int   bn[8];
#pragma unroll
    for (int s = 0; s < 8; s++) { bv[s] = 3.4e38f; bn[s] = 0; }

    stage(gid, 0);
    gbar();

    const int NT = (KCB / CHUNK) / NGRP;   // 32 chunks per group
    for (int t = 0; t < NT; t++) {
        const int ch  = NGRP * t + gid;
        const int buf = t & 1;
        if (t + 1 < NT) stage(NGRP * (t + 1) + gid, buf ^ 1);

        const uint32_t sb1 = (uint32_t)__cvta_generic_to_shared(&smC[gid][buf][0][0]) + lmoff;
        const uint32_t sb2 = (uint32_t)__cvta_generic_to_shared(&smC[gid][buf][1][0]) + lmoff;

#pragma unroll
        for (int no = 0; no < CHUNK; no += 16) {
            uint32_t b1[4], b2[4];
            ldsm_x4(b1[0], b1[1], b1[2], b1[3], sb1 + no * 32);
            ldsm_x4(b2[0], b2[1], b2[2], b2[3], sb2 + no * 32);

            float2 h0 = *(const float2*)&smH[gid][buf][no + kp];
            float2 h1 = *(const float2*)&smH[gid][buf][no + 8 + kp];

            float D0a = h0.x, D0b = h0.y, D0c = h0.x, D0d = h0.y;
            float D1a = h1.x, D1b = h1.y, D1c = h1.x, D1d = h1.y;

            mma_fp16(D0a,D0b,D0c,D0d, a1[0],a1[1],a1[2],a1[3], b1[0],b1[1]);
            mma_fp16(D1a,D1b,D1c,D1d, a1[0],a1[1],a1[2],a1[3], b1[2],b1[3]);
            mma_fp16(D0a,D0b,D0c,D0d, a1[0],a1[1],a1[2],a1[3], b2[0],b2[1]);
            mma_fp16(D1a,D1b,D1c,D1d, a1[0],a1[1],a1[2],a1[3], b2[2],b2[3]);
            mma_fp16(D0a,D0b,D0c,D0d, a2[0],a2[1],a2[2],a2[3], b1[0],b1[1]);
            mma_fp16(D1a,D1b,D1c,D1d, a2[0],a2[1],a2[2],a2[3], b1[2],b1[3]);

            const int nb0 = ch * CHUNK + no;
            const int nb1 = nb0 + 8;
            if (D0a < bv[0]) { bv[0] = D0a; bn[0] = nb0; }
            if (D0b < bv[1]) { bv[1] = D0b; bn[1] = nb0; }
            if (D0c < bv[2]) { bv[2] = D0c; bn[2] = nb0; }
            if (D0d < bv[3]) { bv[3] = D0d; bn[3] = nb0; }
            if (D1a < bv[4]) { bv[4] = D1a; bn[4] = nb1; }
            if (D1b < bv[5]) { bv[5] = D1b; bn[5] = nb1; }
            if (D1c < bv[6]) { bv[6] = D1c; bn[6] = nb1; }
            if (D1d < bv[7]) { bv[7] = D1d; bn[7] = nb1; }
        }
        gbar();
    }

    // ---- in-warp merge: per writer lane, rows r4 and 8+r4 ----
    float vA = 3.4e38f, vB = 3.4e38f;
    int iA = 0x7FFFFFFF, iB = 0x7FFFFFFF;
#pragma unroll
    for (int s = 0; s < 8; s++) {
        int idx = bn[s] + kp + (s & 1);
        bool rowB = (s >> 1) & 1;
        if (!rowB) { if (bv[s] < vA || (bv[s] == vA && idx < iA)) { vA = bv[s]; iA = idx; } }
        else       { if (bv[s] < vB || (bv[s] == vB && idx < iB)) { vB = bv[s]; iB = idx; } }
    }
#pragma unroll
    for (int ofs = 1; ofs <= 2; ofs <<= 1) {
        float v = __shfl_xor_sync(0xFFFFFFFFu, vA, ofs);
        int   i = __shfl_xor_sync(0xFFFFFFFFu, iA, ofs);
        if (v < vA || (v == vA && i < iA)) { vA = v; iA = i; }
        v = __shfl_xor_sync(0xFFFFFFFFu, vB, ofs);
        i = __shfl_xor_sync(0xFFFFFFFFu, iB, ofs);
        if (v < vB || (v == vB && i < iB)) { vB = v; iB = i; }
    }

    // ---- cross-group merge via smem ----
    const int lrowA = w4 * 16 + r4;
    const int lrowB = lrowA + 8;
    if ((lane & 3) == 0) {
        mv[gid][lrowA] = vA; mi[gid][lrowA] = iA;
        mv[gid][lrowB] = vB; mi[gid][lrowB] = iB;
    }
    __syncthreads();
    if (gid == 0 && (lane & 3) == 0) {
#pragma unroll
        for (int g = 1; g < NGRP; g++) {
            float v0 = mv[g][lrowA]; int i0 = mi[g][lrowA];
            if (v0 < vA || (v0 == vA && i0 < iA)) { vA = v0; iA = i0; }
            float v1 = mv[g][lrowB]; int i1 = mi[g][lrowB];
            if (v1 < vB || (v1 == vB && i1 < iB)) { vB = v1; iB = i1; }
        }
        out[blockIdx.x * 64 + lrowA] = (float)iA;
        out[blockIdx.x * 64 + lrowB] = (float)iB;
    }
}

// ---------------- launch -----------------------------------------------------
extern "C" void kernel_launch(void* const* d_in, const int* in_sizes, int n_in,
                              void* d_out, int out_size) {
    int a = 0, b = 1, c = 2;
    if (n_in >= 3) {
        if (in_sizes[a] < in_sizes[b]) { int t = a; a = b; b = t; }
        if (in_sizes[b] < in_sizes[c]) { int t = b; b = c; c = t; }
        if (in_sizes[a] < in_sizes[b]) { int t = a; a = b; b = t; }
    }
    const float* x  = (const float*)d_in[a];
    const float* cb = (const float*)d_in[b];
    const float* W  = (const float*)d_in[c];
    float* out = (float*)d_out;

    k_prep<<<KCB / 128, 128>>>(cb);
    k_proj<<<NROWS / 32, 256>>>(x, W);
    k_dist<<<NROWS / 64, 512>>>(out);
}

// round 16
// speedup vs baseline: 1.0854x; 1.0854x over previous
#include <cuda_runtime.h>
#include <cuda_fp16.h>
#include <cstdint>

// Shapes (fixed by reference setup_inputs)
#define NROWS 16384
#define DDIM  512
#define DC    16
#define KCB   8192
#define LN_EPS 1e-5f

// ---------------- device scratch (no allocation allowed) --------------------
__device__ __half g_h1h[NROWS * DC], g_h2h[NROWS * DC];
__device__ __half g_c1h[KCB * DC],   g_c2h[KCB * DC];
__device__ float  g_hc2[KCB];        // 0.5 * sum c^2

// ---------------- helpers ---------------------------------------------------
__device__ __forceinline__ void split2(float v, __half& s1, __half& s2) {
    s1 = __float2half_rn(v);
    s2 = __float2half_rn(v - __half2float(s1));
}
__device__ __forceinline__ uint32_t pack_h2(__half lo, __half hi) {
    uint16_t a = __half_as_ushort(lo), b = __half_as_ushort(hi);
    return (uint32_t)a | ((uint32_t)b << 16);
}

__device__ __forceinline__ void mma_fp16(float& d0, float& d1, float& d2, float& d3,
                                         uint32_t a0, uint32_t a1, uint32_t a2, uint32_t a3,
                                         uint32_t b0, uint32_t b1) {
    asm volatile(
        "mma.sync.aligned.m16n8k16.row.col.f32.f16.f16.f32 "
        "{%0,%1,%2,%3}, {%4,%5,%6,%7}, {%8,%9}, {%0,%1,%2,%3};"
        : "+f"(d0), "+f"(d1), "+f"(d2), "+f"(d3)
        : "r"(a0), "r"(a1), "r"(a2), "r"(a3), "r"(b0), "r"(b1));
}

__device__ __forceinline__ void ldsm_x4(uint32_t& r0, uint32_t& r1,
                                        uint32_t& r2, uint32_t& r3, uint32_t saddr) {
    asm volatile("ldmatrix.sync.aligned.m8n8.x4.shared.b16 {%0,%1,%2,%3}, [%4];"
                 : "=r"(r0), "=r"(r1), "=r"(r2), "=r"(r3) : "r"(saddr));
}

// ---------------- kernel 1: FUSED codebook prep + projection/LayerNorm ------
// blocks [0,512): projection for 32 rows each (R14 k_proj, unchanged math)
// blocks [512,544): codebook fp16 split-2 pack + half-norms (256 codes each)
__global__ void __launch_bounds__(256) k_pp(
    const float* __restrict__ x, const float* __restrict__ W,
    const float* __restrict__ cb)
{
    if (blockIdx.x >= 512) {
        // ---- prep part ----
        const int k = (blockIdx.x - 512) * 256 + threadIdx.x;
        const float4* c4 = (const float4*)(cb + (size_t)k * DC);
        float4 q0 = c4[0], q1 = c4[1], q2 = c4[2], q3 = c4[3];
        float cv[DC] = {q0.x, q0.y, q0.z, q0.w, q1.x, q1.y, q1.z, q1.w,
                        q2.x, q2.y, q2.z, q2.w, q3.x, q3.y, q3.z, q3.w};
        float c2 = 0.f;
#pragma unroll
        for (int j = 0; j < DC; j++) c2 = fmaf(cv[j], cv[j], c2);
        g_hc2[k] = 0.5f * c2;

        uint32_t p1[8], p2[8];
#pragma unroll
        for (int j = 0; j < 8; j++) {
            __half a1, a2, b1, b2;
            split2(cv[2 * j], a1, a2);
            split2(cv[2 * j + 1], b1, b2);
            p1[j] = pack_h2(a1, b1);
            p2[j] = pack_h2(a2, b2);
        }
        ((uint4*)&g_c1h[k * DC])[0] = *(uint4*)&p1[0];
        ((uint4*)&g_c1h[k * DC])[1] = *(uint4*)&p1[4];
        ((uint4*)&g_c2h[k * DC])[0] = *(uint4*)&p2[0];
        ((uint4*)&g_c2h[k * DC])[1] = *(uint4*)&p2[4];
        return;
    }

    // ---- projection part ----
    const int warp = threadIdx.x >> 5;
    const int lane = threadIdx.x & 31;
    const int rowBase = (blockIdx.x * 8 + warp) * 4;

    float acc[4][DC];
#pragma unroll
    for (int r = 0; r < 4; r++)
#pragma unroll
        for (int j = 0; j < DC; j++) acc[r][j] = 0.f;

#pragma unroll 2
    for (int it = 0; it < DDIM / 32; it++) {
        const int d = it * 32 + lane;
        float wv[DC];
#pragma unroll
        for (int j = 0; j < DC; j++) wv[j] = W[j * DDIM + d];
#pragma unroll
        for (int r = 0; r < 4; r++) {
            float xv = x[(size_t)(rowBase + r) * DDIM + d];
#pragma unroll
            for (int j = 0; j < DC; j++)
                acc[r][j] = fmaf(xv, wv[j], acc[r][j]);
        }
    }

#pragma unroll
    for (int r = 0; r < 4; r++) {
        const int row = rowBase + r;
#pragma unroll
        for (int j = 0; j < DC; j++) {
#pragma unroll
            for (int ofs = 16; ofs > 0; ofs >>= 1)
                acc[r][j] += __shfl_xor_sync(0xFFFFFFFFu, acc[r][j], ofs);
        }

        float s = 0.f;
#pragma unroll
        for (int j = 0; j < DC; j++) s += acc[r][j];
        float mu = s * (1.0f / DC);
        float v = 0.f;
#pragma unroll
        for (int j = 0; j < DC; j++) { float d = acc[r][j] - mu; v = fmaf(d, d, v); }
        float denom = sqrtf(v * (1.0f / DC) + LN_EPS);

        if (lane < 8) {
            float e0 = (mu - acc[r][2 * lane]) / denom;
            float e1 = (mu - acc[r][2 * lane + 1]) / denom;
            __half a1, a2, b1, b2;
            split2(e0, a1, a2);
            split2(e1, b1, b2);
            ((uint32_t*)&g_h1h[row * DC])[lane] = pack_h2(a1, b1);
            ((uint32_t*)&g_h2h[row * DC])[lane] = pack_h2(a2, b2);
        }
    }
}

// ---------------- kernel 2: tensor-core distance + argmin (2 groups x 256) --
// 256 blocks x 256 threads (8 warps = 2 groups of 4). Block owns 64 rows.
// Group g scans chunks 2t+g of 256 codes: 32 barriers/warp, 16-iter runs.
#define CHUNK 256
#define NGRP  2
// dynamic smem layout (bytes):
//   smC(g,buf,split) : (((g*2)+buf)*2+split) * 8192      [4 x 2 x 8192 = 65536]
//   smH(g,buf)       : 65536 + (g*2+buf) * 1024          [4 KB]
//   mv               : 69632  (2 groups x 64 floats)     [512 B]
//   mi               : 70144  (2 groups x 64 ints)       [512 B]
#define SMEM_TOTAL 70656

__global__ void __launch_bounds__(256) k_dist(float* __restrict__ out) {
    extern __shared__ char dsm[];

    const int tid    = threadIdx.x;
    const int warp   = tid >> 5;
    const int lane   = tid & 31;
    const int gid    = warp >> 2;        // 0 or 1
    const int w4     = warp & 3;
    const int tid128 = tid & 127;
    const int row0   = blockIdx.x * 64 + w4 * 16;
    const int r4     = lane >> 2;
    const int kp     = (lane & 3) * 2;

    char* smCg = dsm + gid * 2 * 2 * 8192;               // this group's buffers
    float* smHg = (float*)(dsm + 65536 + gid * 2 * 1024);
    float* mv = (float*)(dsm + 69632);
    int*   mi = (int*)(dsm + 70144);

    // loop-invariant A fragments (layout validated R10-R15)
    uint32_t a1[4], a2[4];
    a1[0] = *(const uint32_t*)&g_h1h[(row0 + r4) * DC + kp];
    a1[1] = *(const uint32_t*)&g_h1h[(row0 + 8 + r4) * DC + kp];
    a1[2] = *(const uint32_t*)&g_h1h[(row0 + r4) * DC + kp + 8];
    a1[3] = *(const uint32_t*)&g_h1h[(row0 + 8 + r4) * DC + kp + 8];
    a2[0] = *(const uint32_t*)&g_h2h[(row0 + r4) * DC + kp];
    a2[1] = *(const uint32_t*)&g_h2h[(row0 + 8 + r4) * DC + kp];
    a2[2] = *(const uint32_t*)&g_h2h[(row0 + r4) * DC + kp + 8];
    a2[3] = *(const uint32_t*)&g_h2h[(row0 + 8 + r4) * DC + kp + 8];

    // stage one 256-code chunk: 512 uint4 per split (4/thread), 1KB hc2
    auto stage = [&](int ch, int buf) {
        uint4* d1 = (uint4*)(smCg + buf * 2 * 8192);
        uint4* d2 = (uint4*)(smCg + buf * 2 * 8192 + 8192);
        const uint4* s1 = ((const uint4*)g_c1h) + ch * 512;
        const uint4* s2 = ((const uint4*)g_c2h) + ch * 512;
#pragma unroll
        for (int i = 0; i < 4; i++) {
            d1[tid128 + i * 128] = s1[tid128 + i * 128];
            d2[tid128 + i * 128] = s2[tid128 + i * 128];
        }
        if (tid128 < 64)
            ((uint4*)(smHg + buf * 256))[tid128] = ((const uint4*)(g_hc2 + ch * CHUNK))[tid128];
    };
    auto gbar = [&]() {
        asm volatile("bar.sync %0, 128;" :: "r"(gid + 1) : "memory");
    };

    const int coderow = (lane & 7) + ((lane & 16) >> 1);
    const int khalf   = (lane >> 3) & 1;
    const uint32_t lmoff = (uint32_t)(coderow * 32 + khalf * 16);

    float bv[8];
    int   bn[8];
#pragma unroll
    for (int s = 0; s < 8; s++) { bv[s] = 3.4e38f; bn[s] = 0; }

    stage(gid, 0);
    gbar();

    const int NT = (KCB / CHUNK) / NGRP;   // 16 chunks per group
    for (int t = 0; t < NT; t++) {
        const int ch  = NGRP * t + gid;
        const int buf = t & 1;
        if (t + 1 < NT) stage(NGRP * (t + 1) + gid, buf ^ 1);

        const uint32_t sb1 =
            (uint32_t)__cvta_generic_to_shared(smCg + buf * 2 * 8192) + lmoff;
        const uint32_t sb2 = sb1 + 8192;
        const float* hh = smHg + buf * 256;

#pragma unroll 4
        for (int no = 0; no < CHUNK; no += 16) {
            uint32_t b1[4], b2[4];
            ldsm_x4(b1[0], b1[1], b1[2], b1[3], sb1 + no * 32);
            ldsm_x4(b2[0], b2[1], b2[2], b2[3], sb2 + no * 32);

            float2 h0 = *(const float2*)&hh[no + kp];
            float2 h1 = *(const float2*)&hh[no + 8 + kp];

            float D0a = h0.x, D0b = h0.y, D0c = h0.x, D0d = h0.y;
            float D1a = h1.x, D1b = h1.y, D1c = h1.x, D1d = h1.y;

            mma_fp16(D0a,D0b,D0c,D0d, a1[0],a1[1],a1[2],a1[3], b1[0],b1[1]);
            mma_fp16(D1a,D1b,D1c,D1d, a1[0],a1[1],a1[2],a1[3], b1[2],b1[3]);
            mma_fp16(D0a,D0b,D0c,D0d, a1[0],a1[1],a1[2],a1[3], b2[0],b2[1]);
            mma_fp16(D1a,D1b,D1c,D1d, a1[0],a1[1],a1[2],a1[3], b2[2],b2[3]);
            mma_fp16(D0a,D0b,D0c,D0d, a2[0],a2[1],a2[2],a2[3], b1[0],b1[1]);
            mma_fp16(D1a,D1b,D1c,D1d, a2[0],a2[1],a2[2],a2[3], b1[2],b1[3]);

            const int nb0 = ch * CHUNK + no;
            const int nb1 = nb0 + 8;
            if (D0a < bv[0]) { bv[0] = D0a; bn[0] = nb0; }
            if (D0b < bv[1]) { bv[1] = D0b; bn[1] = nb0; }
            if (D0c < bv[2]) { bv[2] = D0c; bn[2] = nb0; }
            if (D0d < bv[3]) { bv[3] = D0d; bn[3] = nb0; }
            if (D1a < bv[4]) { bv[4] = D1a; bn[4] = nb1; }
            if (D1b < bv[5]) { bv[5] = D1b; bn[5] = nb1; }
            if (D1c < bv[6]) { bv[6] = D1c; bn[6] = nb1; }
            if (D1d < bv[7]) { bv[7] = D1d; bn[7] = nb1; }
        }
        gbar();
    }

    // ---- in-warp merge: per writer lane, rows r4 and 8+r4 ----
    float vA = 3.4e38f, vB = 3.4e38f;
    int iA = 0x7FFFFFFF, iB = 0x7FFFFFFF;
#pragma unroll
    for (int s = 0; s < 8; s++) {
        int idx = bn[s] + kp + (s & 1);
        bool rowB = (s >> 1) & 1;
        if (!rowB) { if (bv[s] < vA || (bv[s] == vA && idx < iA)) { vA = bv[s]; iA = idx; } }
        else       { if (bv[s] < vB || (bv[s] == vB && idx < iB)) { vB = bv[s]; iB = idx; } }
    }
#pragma unroll
    for (int ofs = 1; ofs <= 2; ofs <<= 1) {
        float v = __shfl_xor_sync(0xFFFFFFFFu, vA, ofs);
        int   i = __shfl_xor_sync(0xFFFFFFFFu, iA, ofs);
        if (v < vA || (v == vA && i < iA)) { vA = v; iA = i; }
        v = __shfl_xor_sync(0xFFFFFFFFu, vB, ofs);
        i = __shfl_xor_sync(0xFFFFFFFFu, iB, ofs);
        if (v < vB || (v == vB && i < iB)) { vB = v; iB = i; }
    }

    // ---- cross-group merge via smem (scores computed once per (row,code)) --
    const int lrowA = w4 * 16 + r4;
    const int lrowB = lrowA + 8;
    if (gid == 0 && (lane & 3) == 0) {
        mv[lrowA] = vA; mi[lrowA] = iA;
        mv[lrowB] = vB; mi[lrowB] = iB;
    }
    __syncthreads();
    if (gid == 1 && (lane & 3) == 0) {
        float v0 = mv[lrowA]; int i0 = mi[lrowA];
        if (v0 < vA || (v0 == vA && i0 < iA)) { vA = v0; iA = i0; }
        float v1 = mv[lrowB]; int i1 = mi[lrowB];
        if (v1 < vB || (v1 == vB && i1 < iB)) { vB = v1; iB = i1; }
        out[blockIdx.x * 64 + lrowA] = (float)iA;
        out[blockIdx.x * 64 + lrowB] = (float)iB;
    }
}

// ---------------- launch -----------------------------------------------------
extern "C" void kernel_launch(void* const* d_in, const int* in_sizes, int n_in,
                              void* d_out, int out_size) {
    int a = 0, b = 1, c = 2;
    if (n_in >= 3) {
        if (in_sizes[a] < in_sizes[b]) { int t = a; a = b; b = t; }
        if (in_sizes[b] < in_sizes[c]) { int t = b; b = c; c = t; }
        if (in_sizes[a] < in_sizes[b]) { int t = a; a = b; b = t; }
    }
    const float* x  = (const float*)d_in[a];
    const float* cb = (const float*)d_in[b];
    const float* W  = (const float*)d_in[c];
    float* out = (float*)d_out;

    // One-time attribute set: happens on the (uncaptured) correctness call.
    static bool attr_set = false;
    if (!attr_set) {
        cudaFuncSetAttribute(k_dist, cudaFuncAttributeMaxDynamicSharedMemorySize,
                             SMEM_TOTAL);
        attr_set = true;
    }

    k_pp<<<544, 256>>>(x, W, cb);
    k_dist<<<NROWS / 64, 256, SMEM_TOTAL>>>(out);
}

// round 17
// speedup vs baseline: 1.2670x; 1.1672x over previous
#include <cuda_runtime.h>
#include <cuda_fp16.h>
#include <cstdint>

// Shapes (fixed by reference setup_inputs)
#define NROWS 16384
#define DDIM  512
#define DC    16
#define KCB   8192
#define LN_EPS 1e-5f

// ---------------- device scratch (no allocation allowed) --------------------
__device__ __half g_h1h[NROWS * DC], g_h2h[NROWS * DC];
__device__ __half g_c1h[KCB * DC],   g_c2h[KCB * DC];
__device__ float  g_hc2[KCB];        // 0.5 * sum c^2

// ---------------- helpers ---------------------------------------------------
__device__ __forceinline__ void split2(float v, __half& s1, __half& s2) {
    s1 = __float2half_rn(v);
    s2 = __float2half_rn(v - __half2float(s1));
}
__device__ __forceinline__ uint32_t pack_h2(__half lo, __half hi) {
    uint16_t a = __half_as_ushort(lo), b = __half_as_ushort(hi);
    return (uint32_t)a | ((uint32_t)b << 16);
}

__device__ __forceinline__ void mma_fp16(float& d0, float& d1, float& d2, float& d3,
                                         uint32_t a0, uint32_t a1, uint32_t a2, uint32_t a3,
                                         uint32_t b0, uint32_t b1) {
    asm volatile(
        "mma.sync.aligned.m16n8k16.row.col.f32.f16.f16.f32 "
        "{%0,%1,%2,%3}, {%4,%5,%6,%7}, {%8,%9}, {%0,%1,%2,%3};"
        : "+f"(d0), "+f"(d1), "+f"(d2), "+f"(d3)
        : "r"(a0), "r"(a1), "r"(a2), "r"(a3), "r"(b0), "r"(b1));
}

__device__ __forceinline__ void ldsm_x4(uint32_t& r0, uint32_t& r1,
                                        uint32_t& r2, uint32_t& r3, uint32_t saddr) {
    asm volatile("ldmatrix.sync.aligned.m8n8.x4.shared.b16 {%0,%1,%2,%3}, [%4];"
                 : "=r"(r0), "=r"(r1), "=r"(r2), "=r"(r3) : "r"(saddr));
}

__device__ __forceinline__ void cp16(uint32_t saddr, const void* gptr) {
    asm volatile("cp.async.cg.shared.global [%0], [%1], 16;"
                 :: "r"(saddr), "l"(gptr));
}
__device__ __forceinline__ void cp_commit() {
    asm volatile("cp.async.commit_group;" ::: "memory");
}
__device__ __forceinline__ void cp_wait0() {
    asm volatile("cp.async.wait_group 0;" ::: "memory");
}

// ---------------- kernel 1: FUSED codebook prep + projection/LayerNorm ------
__global__ void __launch_bounds__(256) k_pp(
    const float* __restrict__ x, const float* __restrict__ W,
    const float* __restrict__ cb)
{
    if (blockIdx.x >= 512) {
        const int k = (blockIdx.x - 512) * 256 + threadIdx.x;
        const float4* c4 = (const float4*)(cb + (size_t)k * DC);
        float4 q0 = c4[0], q1 = c4[1], q2 = c4[2], q3 = c4[3];
        float cv[DC] = {q0.x, q0.y, q0.z, q0.w, q1.x, q1.y, q1.z, q1.w,
                        q2.x, q2.y, q2.z, q2.w, q3.x, q3.y, q3.z, q3.w};
        float c2 = 0.f;
#pragma unroll
        for (int j = 0; j < DC; j++) c2 = fmaf(cv[j], cv[j], c2);
        g_hc2[k] = 0.5f * c2;

        uint32_t p1[8], p2[8];
#pragma unroll
        for (int j = 0; j < 8; j++) {
            __half a1, a2, b1, b2;
            split2(cv[2 * j], a1, a2);
            split2(cv[2 * j + 1], b1, b2);
            p1[j] = pack_h2(a1, b1);
            p2[j] = pack_h2(a2, b2);
        }
        ((uint4*)&g_c1h[k * DC])[0] = *(uint4*)&p1[0];
        ((uint4*)&g_c1h[k * DC])[1] = *(uint4*)&p1[4];
        ((uint4*)&g_c2h[k * DC])[0] = *(uint4*)&p2[0];
        ((uint4*)&g_c2h[k * DC])[1] = *(uint4*)&p2[4];
        return;
    }

    const int warp = threadIdx.x >> 5;
    const int lane = threadIdx.x & 31;
    const int rowBase = (blockIdx.x * 8 + warp) * 4;

    float acc[4][DC];
#pragma unroll
    for (int r = 0; r < 4; r++)
#pragma unroll
        for (int j = 0; j < DC; j++) acc[r][j] = 0.f;

#pragma unroll 2
    for (int it = 0; it < DDIM / 32; it++) {
        const int d = it * 32 + lane;
        float wv[DC];
#pragma unroll
        for (int j = 0; j < DC; j++) wv[j] = W[j * DDIM + d];
#pragma unroll
        for (int r = 0; r < 4; r++) {
            float xv = x[(size_t)(rowBase + r) * DDIM + d];
#pragma unroll
            for (int j = 0; j < DC; j++)
                acc[r][j] = fmaf(xv, wv[j], acc[r][j]);
        }
    }

#pragma unroll
    for (int r = 0; r < 4; r++) {
        const int row = rowBase + r;
#pragma unroll
        for (int j = 0; j < DC; j++) {
#pragma unroll
            for (int ofs = 16; ofs > 0; ofs >>= 1)
                acc[r][j] += __shfl_xor_sync(0xFFFFFFFFu, acc[r][j], ofs);
        }

        float s = 0.f;
#pragma unroll
        for (int j = 0; j < DC; j++) s += acc[r][j];
        float mu = s * (1.0f / DC);
        float v = 0.f;
#pragma unroll
        for (int j = 0; j < DC; j++) { float d = acc[r][j] - mu; v = fmaf(d, d, v); }
        float denom = sqrtf(v * (1.0f / DC) + LN_EPS);

        if (lane < 8) {
            float e0 = (mu - acc[r][2 * lane]) / denom;
            float e1 = (mu - acc[r][2 * lane + 1]) / denom;
            __half a1, a2, b1, b2;
            split2(e0, a1, a2);
            split2(e1, b1, b2);
            ((uint32_t*)&g_h1h[row * DC])[lane] = pack_h2(a1, b1);
            ((uint32_t*)&g_h2h[row * DC])[lane] = pack_h2(a2, b2);
        }
    }
}

// ---------------- kernel 2: distance + argmin (4 groups x 2 warps, 32 r/w) --
// 256 blocks x 256 threads. Block owns 64 rows. Group g (2 warps) scans chunks
// 4t+g of 128 codes; warp covers 32 rows (two 16-row A sets) -> each LDSM pair
// feeds 12 MMAs. cp.async staging, smem merge at the end.
#define CHUNK 128
#define NGRP  4
// dynamic smem (bytes):
//   smC(g,buf,split): ((g*2+buf)*2+split)*4096   [16 x 4096 = 65536]
//   smH(g,buf): 65536 + (g*2+buf)*512            [4096]
//   mv: 69632 [1024]   mi: 70656 [1024]
#define SMEM_TOTAL 71680

__global__ void __launch_bounds__(256, 2) k_dist(float* __restrict__ out) {
    extern __shared__ char dsm[];

    const int tid  = threadIdx.x;
    const int warp = tid >> 5;
    const int lane = tid & 31;
    const int gid  = warp >> 1;          // 0..3 code-group
    const int w2   = warp & 1;           // row-half of block
    const int gtid = tid & 63;
    const int row0 = blockIdx.x * 64 + w2 * 32;
    const int r4   = lane >> 2;
    const int kp   = (lane & 3) * 2;

    char*  smCg = dsm + gid * 2 * 2 * 4096;
    float* smHg = (float*)(dsm + 65536 + gid * 2 * 512);
    float* mv   = (float*)(dsm + 69632);
    int*   mi   = (int*)(dsm + 70656);

    // A fragments: two 16-row sets (rows row0..+15 and row0+16..+31)
    uint32_t a1[4], a2[4], a3[4], a4[4];
#pragma unroll
    for (int s = 0; s < 2; s++) {
        const int rb = row0 + s * 16;
        uint32_t* p1 = s ? a3 : a1;
        uint32_t* p2 = s ? a4 : a2;
        p1[0] = *(const uint32_t*)&g_h1h[(rb + r4) * DC + kp];
        p1[1] = *(const uint32_t*)&g_h1h[(rb + 8 + r4) * DC + kp];
        p1[2] = *(const uint32_t*)&g_h1h[(rb + r4) * DC + kp + 8];
        p1[3] = *(const uint32_t*)&g_h1h[(rb + 8 + r4) * DC + kp + 8];
        p2[0] = *(const uint32_t*)&g_h2h[(rb + r4) * DC + kp];
        p2[1] = *(const uint32_t*)&g_h2h[(rb + 8 + r4) * DC + kp];
        p2[2] = *(const uint32_t*)&g_h2h[(rb + r4) * DC + kp + 8];
        p2[3] = *(const uint32_t*)&g_h2h[(rb + 8 + r4) * DC + kp + 8];
    }

    // cp.async staging: 256 uint4 per split per chunk, 64 threads -> 4 each
    auto stage = [&](int ch, int buf) {
        uint32_t d1 = (uint32_t)__cvta_generic_to_shared(smCg + buf * 2 * 4096);
        uint32_t d2 = d1 + 4096;
        const uint4* s1 = ((const uint4*)g_c1h) + ch * 256;
        const uint4* s2 = ((const uint4*)g_c2h) + ch * 256;
#pragma unroll
        for (int i = 0; i < 4; i++) {
            cp16(d1 + (gtid + i * 64) * 16, s1 + gtid + i * 64);
            cp16(d2 + (gtid + i * 64) * 16, s2 + gtid + i * 64);
        }
        if (gtid < 32) {
            uint32_t dh = (uint32_t)__cvta_generic_to_shared(smHg + buf * 128);
            cp16(dh + gtid * 16, ((const uint4*)(g_hc2 + ch * CHUNK)) + gtid);
        }
        cp_commit();
    };
    auto gbar = [&]() {
        asm volatile("bar.sync %0, 64;" :: "r"(gid + 1) : "memory");
    };

    const int coderow = (lane & 7) + ((lane & 16) >> 1);
    const int khalf   = (lane >> 3) & 1;
    const uint32_t lmoff = (uint32_t)(coderow * 32 + khalf * 16);

    float bv[16];
    int   bn[16];
#pragma unroll
    for (int s = 0; s < 16; s++) { bv[s] = 3.4e38f; bn[s] = 0; }

    stage(gid, 0);
    cp_wait0();
    gbar();

    const int NT = (KCB / CHUNK) / NGRP;   // 16 chunks per group
    for (int t = 0; t < NT; t++) {
        const int ch  = NGRP * t + gid;
        const int buf = t & 1;
        if (t + 1 < NT) stage(NGRP * (t + 1) + gid, buf ^ 1);

        const uint32_t sb1 =
            (uint32_t)__cvta_generic_to_shared(smCg + buf * 2 * 4096) + lmoff;
        const uint32_t sb2 = sb1 + 4096;
        const float* hh = smHg + buf * 128;

#pragma unroll 2
        for (int no = 0; no < CHUNK; no += 16) {
            uint32_t b1[4], b2[4];
            ldsm_x4(b1[0], b1[1], b1[2], b1[3], sb1 + no * 32);
            ldsm_x4(b2[0], b2[1], b2[2], b2[3], sb2 + no * 32);

            float2 h0 = *(const float2*)&hh[no + kp];
            float2 h1 = *(const float2*)&hh[no + 8 + kp];

            // rowset0 (D), rowset1 (E); nblock0/1; 4 independent 3-chains
            float D0a = h0.x, D0b = h0.y, D0c = h0.x, D0d = h0.y;
            float D1a = h1.x, D1b = h1.y, D1c = h1.x, D1d = h1.y;
            float E0a = h0.x, E0b = h0.y, E0c = h0.x, E0d = h0.y;
            float E1a = h1.x, E1b = h1.y, E1c = h1.x, E1d = h1.y;

            mma_fp16(D0a,D0b,D0c,D0d, a1[0],a1[1],a1[2],a1[3], b1[0],b1[1]);
            mma_fp16(D1a,D1b,D1c,D1d, a1[0],a1[1],a1[2],a1[3], b1[2],b1[3]);
            mma_fp16(E0a,E0b,E0c,E0d, a3[0],a3[1],a3[2],a3[3], b1[0],b1[1]);
            mma_fp16(E1a,E1b,E1c,E1d, a3[0],a3[1],a3[2],a3[3], b1[2],b1[3]);
            mma_fp16(D0a,D0b,D0c,D0d, a1[0],a1[1],a1[2],a1[3], b2[0],b2[1]);
            mma_fp16(D1a,D1b,D1c,D1d, a1[0],a1[1],a1[2],a1[3], b2[2],b2[3]);
            mma_fp16(E0a,E0b,E0c,E0d, a3[0],a3[1],a3[2],a3[3], b2[0],b2[1]);
            mma_fp16(E1a,E1b,E1c,E1d, a3[0],a3[1],a3[2],a3[3], b2[2],b2[3]);
            mma_fp16(D0a,D0b,D0c,D0d, a2[0],a2[1],a2[2],a2[3], b1[0],b1[1]);
            mma_fp16(D1a,D1b,D1c,D1d, a2[0],a2[1],a2[2],a2[3], b1[2],b1[3]);
            mma_fp16(E0a,E0b,E0c,E0d, a4[0],a4[1],a4[2],a4[3], b1[0],b1[1]);
            mma_fp16(E1a,E1b,E1c,E1d, a4[0],a4[1],a4[2],a4[3], b1[2],b1[3]);

            const int nb0 = ch * CHUNK + no;
            const int nb1 = nb0 + 8;
            if (D0a < bv[0])  { bv[0]  = D0a; bn[0]  = nb0; }
            if (D0b < bv[1])  { bv[1]  = D0b; bn[1]  = nb0; }
            if (D0c < bv[2])  { bv[2]  = D0c; bn[2]  = nb0; }
            if (D0d < bv[3])  { bv[3]  = D0d; bn[3]  = nb0; }
            if (D1a < bv[4])  { bv[4]  = D1a; bn[4]  = nb1; }
            if (D1b < bv[5])  { bv[5]  = D1b; bn[5]  = nb1; }
            if (D1c < bv[6])  { bv[6]  = D1c; bn[6]  = nb1; }
            if (D1d < bv[7])  { bv[7]  = D1d; bn[7]  = nb1; }
            if (E0a < bv[8])  { bv[8]  = E0a; bn[8]  = nb0; }
            if (E0b < bv[9])  { bv[9]  = E0b; bn[9]  = nb0; }
            if (E0c < bv[10]) { bv[10] = E0c; bn[10] = nb0; }
            if (E0d < bv[11]) { bv[11] = E0d; bn[11] = nb0; }
            if (E1a < bv[12]) { bv[12] = E1a; bn[12] = nb1; }
            if (E1b < bv[13]) { bv[13] = E1b; bn[13] = nb1; }
            if (E1c < bv[14]) { bv[14] = E1c; bn[14] = nb1; }
            if (E1d < bv[15]) { bv[15] = E1d; bn[15] = nb1; }
        }
        cp_wait0();
        gbar();
    }

    // ---- in-warp merge: 4 output rows per writer lane ----
    // slot -> (rowset s>>3, row-half (s>>1)&1, col parity s&1)
    float vv[4] = {3.4e38f, 3.4e38f, 3.4e38f, 3.4e38f};
    int   ii[4] = {0x7FFFFFFF, 0x7FFFFFFF, 0x7FFFFFFF, 0x7FFFFFFF};
#pragma unroll
    for (int s = 0; s < 16; s++) {
        int idx = bn[s] + kp + (s & 1);
        int slot = ((s >> 3) << 1) | ((s >> 1) & 1);
        if (bv[s] < vv[slot] || (bv[s] == vv[slot] && idx < ii[slot])) {
            vv[slot] = bv[s]; ii[slot] = idx;
        }
    }
#pragma unroll
    for (int ofs = 1; ofs <= 2; ofs <<= 1) {
#pragma unroll
        for (int q = 0; q < 4; q++) {
            float v = __shfl_xor_sync(0xFFFFFFFFu, vv[q], ofs);
            int   i = __shfl_xor_sync(0xFFFFFFFFu, ii[q], ofs);
            if (v < vv[q] || (v == vv[q] && i < ii[q])) { vv[q] = v; ii[q] = i; }
        }
    }

    // ---- cross-group merge via smem ----
    // rows for writer lane: w2*32 + r4 + {0, 8, 16, 24} for slots {0,1,2,3}
    if ((lane & 3) == 0) {
#pragma unroll
        for (int q = 0; q < 4; q++) {
            int lrow = w2 * 32 + r4 + ((q >> 1) * 16) + ((q & 1) * 8);
            mv[gid * 64 + lrow] = vv[q];
            mi[gid * 64 + lrow] = ii[q];
        }
    }
    __syncthreads();
    if (gid == 0 && (lane & 3) == 0) {
#pragma unroll
        for (int q = 0; q < 4; q++) {
            int lrow = w2 * 32 + r4 + ((q >> 1) * 16) + ((q & 1) * 8);
            float v = vv[q]; int i = ii[q];
#pragma unroll
            for (int g = 1; g < NGRP; g++) {
                float v2 = mv[g * 64 + lrow]; int i2 = mi[g * 64 + lrow];
                if (v2 < v || (v2 == v && i2 < i)) { v = v2; i = i2; }
            }
            out[blockIdx.x * 64 + lrow] = (float)i;
        }
    }
}

// ---------------- launch -----------------------------------------------------
extern "C" void kernel_launch(void* const* d_in, const int* in_sizes, int n_in,
                              void* d_out, int out_size) {
    int a = 0, b = 1, c = 2;
    if (n_in >= 3) {
        if (in_sizes[a] < in_sizes[b]) { int t = a; a = b; b = t; }
        if (in_sizes[b] < in_sizes[c]) { int t = b; b = c; c = t; }
        if (in_sizes[a] < in_sizes[b]) { int t = a; a = b; b = t; }
    }
    const float* x  = (const float*)d_in[a];
    const float* cb = (const float*)d_in[b];
    const float* W  = (const float*)d_in[c];
    float* out = (float*)d_out;

    static bool attr_set = false;
    if (!attr_set) {
        cudaFuncSetAttribute(k_dist, cudaFuncAttributeMaxDynamicSharedMemorySize,
                             SMEM_TOTAL);
        attr_set = true;
    }

    k_pp<<<544, 256>>>(x, W, cb);
    k_dist<<<NROWS / 64, 256, SMEM_TOTAL>>>(out);
}